// round 14
// baseline (speedup 1.0000x reference)
#include <cuda_runtime.h>

// GaussianHistogram: hist[b,i,j] = sum_n exp(-pi*(f1-i)^2) * exp(-pi*(f2-j)^2) * mask
// (SIGMA = DELTA/sqrt(2pi) makes the exponent exactly -pi*d^2 and COEF == 1.0.)
//
// Fused single-kernel design (R8: each tiny launch costs ~4us of overhead):
//   phase 1 (scatter): 3 16B-aligned v4 REDs per sample — the L1tex-wavefront
//     floor (fit over R3-R8: ~2.26 cyc per divergent RED-instruction-lane/SM).
//     Alignment is guaranteed by splitting samples between out (r=0) and a
//     column-shifted scratch S2 (r=2), r = (i2-1)&2.
//   grid barrier: arrive+spin counter; 512 blocks with __launch_bounds__(256,4)
//     -> >=592 co-resident blocks, no deadlock.
//   phase 2 (fold): THREAD-LOCAL. Each thread reads only its OWN S2 float4
//     (cols j..j+3), REDs it into out at cols j+2..j+5 via two 8B-aligned v2
//     REDs (coalesced), and zero-stores only its own slot. No neighbor-slot
//     reads -> no race (the R12 failure was thread t zeroing the slot thread
//     t+1 was still reading).
//   S2 cols 252..255 are never written by the scatter (windows end <= 251),
//   so boundary slots are permanently zero and their REDs are skipped
//   deterministically -> no cross-row or OOB RED.

#define GH_BINS    256
#define GH_LOGN    15                 // N = 32768 per batch
#define GH_TOTALH  (8 * 65536)        // B * BINS * BINS = 524288
#define GH_GRID    512
#define GH_THREADS 256
#define GH_STRIDE  (GH_GRID * GH_THREADS)   // 131072

__device__ float gh_s2[GH_TOTALH];            // 2 MB, zero-invariant
__device__ unsigned int gh_bar  = 0;
__device__ unsigned int gh_done = 0;

__device__ __forceinline__ void gh_scatter_one(int idx,
                                               const float* __restrict__ x1,
                                               const float* __restrict__ x2,
                                               const float* __restrict__ mask,
                                               float* __restrict__ out)
{
    int b = idx >> GH_LOGN;           // batch index (N = 32768)

    float a1 = x1[idx];
    float a2 = x2[idx];
    float m  = mask[idx];

    // continuous bin coordinate: f = (x - MIN_V)/DELTA - 0.5 ; center c_i at f == i
    const float INV_DELTA = 256.0f / 1.5f;
    float f1 = (a1 + 0.25f) * INV_DELTA - 0.5f;
    float f2 = (a2 + 0.25f) * INV_DELTA - 0.5f;

    int i1 = (int)floorf(f1 + 0.5f);
    int i2 = (int)floorf(f2 + 0.5f);
    i1 = min(max(i1, 1), GH_BINS - 2);     // OOB insurance (x in [0,1))
    i2 = min(max(i2, 1), GH_BINS - 2);

    float u1 = f1 - (float)i1;
    float u2 = f2 - (float)i2;

    const float NPI_L2E = -4.53236014182719f;   // -pi * log2(e)

    float dm = u1 + 1.0f, dp = u1 - 1.0f;
    float w0 = exp2f(NPI_L2E * dm * dm);
    float w1 = exp2f(NPI_L2E * u1 * u1);
    float w2 = exp2f(NPI_L2E * dp * dp);

    float em = u2 + 1.0f, ep = u2 - 1.0f;
    float t0 = exp2f(NPI_L2E * em * em) * m;
    float t1 = exp2f(NPI_L2E * u2 * u2) * m;
    float t2 = exp2f(NPI_L2E * ep * ep) * m;

    // taps at cols a..a+2, a = i2-1 in [0,253].
    // r = a&2: with am = a-r, am&3 in {0,1} -> taps fit one aligned v4 window.
    int a   = i2 - 1;
    int r   = a & 2;                  // 0 -> out, 2 -> S2 replica (shifted -2)
    int am  = a - r;
    int w   = am & ~3;                // window start, [0,248]
    bool od = (am & 1) != 0;

    float g0 = od ? 0.0f : t0;
    float g1 = od ? t0   : t1;
    float g2 = od ? t1   : t2;
    float g3 = od ? t2   : 0.0f;

    size_t off = ((size_t)b << 16) + (size_t)(i1 - 1) * GH_BINS + w;
    float* base = (r == 0) ? (out + off) : (gh_s2 + off);

    float p0 = w0*g0, p1 = w0*g1, p2 = w0*g2, p3 = w0*g3;
    asm volatile("red.global.add.v4.f32 [%0], {%1,%2,%3,%4};"
                 :: "l"(base), "f"(p0), "f"(p1), "f"(p2), "f"(p3) : "memory");
    p0 = w1*g0; p1 = w1*g1; p2 = w1*g2; p3 = w1*g3;
    asm volatile("red.global.add.v4.f32 [%0], {%1,%2,%3,%4};"
                 :: "l"(base + GH_BINS), "f"(p0), "f"(p1), "f"(p2), "f"(p3) : "memory");
    p0 = w2*g0; p1 = w2*g1; p2 = w2*g2; p3 = w2*g3;
    asm volatile("red.global.add.v4.f32 [%0], {%1,%2,%3,%4};"
                 :: "l"(base + 2*GH_BINS), "f"(p0), "f"(p1), "f"(p2), "f"(p3) : "memory");
}

__global__ void __launch_bounds__(GH_THREADS, 4)
gh_fused_kernel(const float* __restrict__ x1,
                const float* __restrict__ x2,
                const float* __restrict__ mask,
                float* __restrict__ out,
                int total)
{
    int t = blockIdx.x * GH_THREADS + threadIdx.x;

    // ---- phase 1: scatter (2 samples per thread) ----
    if (t < total)             gh_scatter_one(t,             x1, x2, mask, out);
    if (t + GH_STRIDE < total) gh_scatter_one(t + GH_STRIDE, x1, x2, mask, out);

    // ---- grid barrier (all 512 blocks co-resident via __launch_bounds__) ----
    __syncthreads();
    if (threadIdx.x == 0) {
        __threadfence();                       // order REDs before arrive
        atomicAdd(&gh_bar, 1u);
        while (*(volatile unsigned int*)&gh_bar < GH_GRID)
            __nanosleep(64);
    }
    __syncthreads();
    __threadfence();                           // acquire side

    // ---- phase 2: thread-local fold ----
    // thread t owns S2 float4 at element index base = 4t (exact cover:
    // 131072 threads * 4 = 524288). S2[b,i,jj] contributes to out[b,i,jj+2]:
    // push own cols j..j+3 into out cols j+2..j+5 with two v2 REDs, zero own slot.
    {
        int base = t * 4;
        float4 v = *reinterpret_cast<const float4*>(gh_s2 + base);

        float s = fabsf(v.x) + fabsf(v.y) + fabsf(v.z) + fabsf(v.w);
        if (s != 0.0f) {
            // nonzero implies col <= 251, so base+5 stays within this row
            asm volatile("red.global.add.v2.f32 [%0], {%1,%2};"
                         :: "l"(out + base + 2), "f"(v.x), "f"(v.y) : "memory");
            asm volatile("red.global.add.v2.f32 [%0], {%1,%2};"
                         :: "l"(out + base + 4), "f"(v.z), "f"(v.w) : "memory");
        }
        // restore zero invariant: each thread zeroes ONLY its own slot
        *reinterpret_cast<float4*>(gh_s2 + base) = make_float4(0.f, 0.f, 0.f, 0.f);
    }

    // ---- counter self-reset for the next graph replay ----
    __syncthreads();
    if (threadIdx.x == 0) {
        __threadfence();
        unsigned int vdone = atomicAdd(&gh_done, 1u);
        if (vdone == GH_GRID - 1) {            // last block: all are past gh_bar
            gh_bar  = 0;
            gh_done = 0;
            __threadfence();
        }
    }
}

extern "C" void kernel_launch(void* const* d_in, const int* in_sizes, int n_in,
                              void* d_out, int out_size)
{
    const float* x1   = (const float*)d_in[0];
    const float* x2   = (const float*)d_in[1];
    const float* mask = (const float*)d_in[2];
    float* out = (float*)d_out;

    // out accumulates REDs directly -> zero it (memset node; graph-capturable)
    cudaMemsetAsync(d_out, 0, (size_t)out_size * sizeof(float));

    int total = in_sizes[0];               // B*N = 262144
    gh_fused_kernel<<<GH_GRID, GH_THREADS>>>(x1, x2, mask, out, total);
}